// round 14
// baseline (speedup 1.0000x reference)
#include <cuda_runtime.h>
#include <cuda_bf16.h>
#include <cuda_fp16.h>
#include <cstdint>

// ---------------- problem dims ----------------
#define BATCH 64
#define SEQ   512
#define ISZ   512
#define HSZ   1024
#define GSZ   4096
#define NCTA  128            // 2 batch-groups x 64 column-groups
#define NCG   64             // column groups
#define UPC   16             // hidden units per cg (64 gate cols, col = ui*4+gate)
#define MB    32             // batches per CTA
#define WORDS_H (64 * 8 * 32 * 2)      // 32768 u32 per cg (fp16 frags, K=1024, N=64)
#define WORDS_X (32 * 8 * 32 * 2)      // 16384 u32 per cg (K=512, N=64)
#define CBQ   2              // cg blocks per xw CTA
#define NKTX  16             // k32 tiles in x GEMM

// recurrent smem layout (bytes): W 128KB, then ONE A stage (32 rows x k1024)
#define SM_A     131072
#define A_STRIDE 2064                   // 2048B data + 16B pad
#define SMEM_TOTAL (SM_A + 32 * A_STRIDE)   // 197120

// xw smem (dynamic): 3 stages A + 3 stages B
#define XG_A_STAGE 10240     // 128 rows x 80B (fp16 k32)
#define XG_B_STAGE 8192      // 2 cg x 4KB
#define XG_SMEM (3 * (XG_A_STAGE + XG_B_STAGE))   // 55296

// ---------------- persistent device scratch ----------------
__device__ __align__(256) unsigned g_Whf[(size_t)NCG * WORDS_H];      // 8 MB
__device__ __align__(256) unsigned g_Wxf[(size_t)NCG * WORDS_X];      // 4 MB
__device__ __align__(256) __half   g_xh[(size_t)BATCH * SEQ * ISZ];   // 32 MB
__device__ __align__(256) __half   g_xg[(size_t)SEQ * NCG * BATCH * 64]; // 256 MB
__device__ __align__(256) __half   g_h[2][BATCH * HSZ];               // fp16 h, ping-pong
__device__ __align__(128) unsigned g_flags[NCTA * 32];

// ---------------- helpers ----------------
__device__ __forceinline__ void cp_async16_s(uint32_t dst_smem, const void* src) {
    asm volatile("cp.async.cg.shared.global [%0], [%1], 16;\n"
                 :: "r"(dst_smem), "l"(src) : "memory");
}
__device__ __forceinline__ void cp_commit() {
    asm volatile("cp.async.commit_group;\n" ::: "memory");
}
// accurate activations (fast MUFU versions doubled rel_err via biased rounding)
__device__ __forceinline__ float sigmoidf_(float v) { return 1.0f / (1.0f + expf(-v)); }

#define LDSM4(R, ADDR) \
    asm volatile("ldmatrix.sync.aligned.m8n8.x4.shared.b16 {%0,%1,%2,%3},[%4];" \
                 : "=r"((R)[0]), "=r"((R)[1]), "=r"((R)[2]), "=r"((R)[3]) : "r"(ADDR))

#define MMA_F16(ACC, A, B0, B1) \
    asm volatile("mma.sync.aligned.m16n8k16.row.col.f32.f16.f16.f32 " \
                 "{%0,%1,%2,%3},{%4,%5,%6,%7},{%8,%9},{%0,%1,%2,%3};" \
                 : "+f"((ACC)[0]), "+f"((ACC)[1]), "+f"((ACC)[2]), "+f"((ACC)[3]) \
                 : "r"((A)[0]), "r"((A)[1]), "r"((A)[2]), "r"((A)[3]), "r"(B0), "r"(B1))

#define LDSV2(R0, R1, ADDR) \
    asm volatile("ld.shared.v2.u32 {%0,%1},[%2];" : "=r"(R0), "=r"(R1) : "r"(ADDR))

// ---------------- prep kernels ----------------
__global__ void prep_x(const float* __restrict__ x) {
    size_t i = (size_t)blockIdx.x * blockDim.x + threadIdx.x;
    size_t n4 = (size_t)BATCH * SEQ * ISZ / 4;
    if (i >= n4) return;
    float4 v = reinterpret_cast<const float4*>(x)[i];
    __half2* d = reinterpret_cast<__half2*>(g_xh);
    d[i * 2]     = __halves2half2(__float2half_rn(v.x), __float2half_rn(v.y));
    d[i * 2 + 1] = __halves2half2(__float2half_rn(v.z), __float2half_rn(v.w));
}

// Wh fragments fp16 (K=1024, N=64 per cg). Local col nl = ui*4 + gate.
__global__ void prep_wh(const float* __restrict__ W) {
    size_t w = (size_t)blockIdx.x * blockDim.x + threadIdx.x;
    if (w >= (size_t)NCG * WORDS_H) return;
    int q    = (int)(w & 1);
    int lane = (int)((w >> 1) & 31);
    int n8   = (int)((w >> 6) & 7);
    int k16  = (int)((w >> 9) & 63);
    int cg   = (int)(w >> 15);
    int k  = k16 * 16 + (lane & 3) * 2 + q * 8;
    int nl = n8 * 8 + (lane >> 2);
    int gate = nl & 3, ui = nl >> 2;
    int col = gate * HSZ + cg * UPC + ui;
    __half h0 = __float2half_rn(W[(size_t)(ISZ + k) * GSZ + col]);
    __half h1 = __float2half_rn(W[(size_t)(ISZ + k + 1) * GSZ + col]);
    __half2 ph = __halves2half2(h0, h1);
    g_Whf[w] = *reinterpret_cast<unsigned*>(&ph);
}

// Wx fragments fp16 (K=512, N=64 per cg). Same col permutation.
__global__ void prep_wx(const float* __restrict__ W) {
    size_t w = (size_t)blockIdx.x * blockDim.x + threadIdx.x;
    if (w >= (size_t)NCG * WORDS_X) return;
    int q    = (int)(w & 1);
    int lane = (int)((w >> 1) & 31);
    int n8   = (int)((w >> 6) & 7);
    int k16  = (int)((w >> 9) & 31);
    int cg   = (int)(w >> 14);
    int k  = k16 * 16 + (lane & 3) * 2 + q * 8;
    int nl = n8 * 8 + (lane >> 2);
    int gate = nl & 3, ui = nl >> 2;
    int col = gate * HSZ + cg * UPC + ui;
    __half h0 = __float2half_rn(W[(size_t)k * GSZ + col]);
    __half h1 = __float2half_rn(W[(size_t)(k + 1) * GSZ + col]);
    __half2 ph = __halves2half2(h0, h1);
    g_Wxf[w] = *reinterpret_cast<unsigned*>(&ph);
}

__global__ void prep_state() {
    int i = blockIdx.x * blockDim.x + threadIdx.x;
    if (i < 2 * BATCH * HSZ) (&g_h[0][0])[i] = __float2half(0.0f);
    if (i < NCTA * 32) g_flags[i] = 0u;
}

// ---------------- xg precompute GEMM (fp16, K=512) ----------------
__global__ void __launch_bounds__(256) xw_gemm(const float* __restrict__ bias) {
    extern __shared__ char smem[];
    const uint32_t sA_u = (uint32_t)__cvta_generic_to_shared(smem);
    const uint32_t sB_u = sA_u + 3 * XG_A_STAGE;

    const int tid  = threadIdx.x;
    const int warp = tid >> 5;
    const int lane = tid & 31;
    const int bx   = blockIdx.x;
    const int cg0  = blockIdx.y * CBQ;
    const int mw   = warp >> 1;      // 4 M-warps (32 rows each)
    const int nw   = warp & 1;       // cg select (64 cols each)

    float acc[2][8][4];
#pragma unroll
    for (int a = 0; a < 2; a++)
#pragma unroll
        for (int b = 0; b < 8; b++)
#pragma unroll
            for (int c = 0; c < 4; c++) acc[a][b][c] = 0.0f;

    auto load_tile = [&](int kt, int stage) {
        const int k0 = kt * 32;
#pragma unroll
        for (int j = 0; j < 2; j++) {
            int ch = tid + j * 256;
            int rr = ch >> 2, cc = ch & 3;
            cp_async16_s(sA_u + stage * XG_A_STAGE + rr * 80 + cc * 16,
                         g_xh + ((size_t)(bx * 128 + rr)) * ISZ + k0 + cc * 8);
        }
#pragma unroll
        for (int j = 0; j < 2; j++) {
            int ch = tid + j * 256;
            int q = ch >> 8, ww = ch & 255;
            const unsigned* src = g_Wxf + (size_t)(cg0 + q) * WORDS_X + kt * 1024 + ww * 4;
            cp_async16_s(sB_u + stage * XG_B_STAGE + q * 4096 + ww * 16, src);
        }
        cp_commit();
    };

    load_tile(0, 0);
    load_tile(1, 1);

    const uint32_t arow = (uint32_t)((mw * 32 + (lane & 15)) * 80 + (lane >> 4) * 16);

#pragma unroll
    for (int kt = 0; kt < NKTX; kt++) {
        if (kt == NKTX - 1) { asm volatile("cp.async.wait_group 0;\n" ::: "memory"); }
        else                { asm volatile("cp.async.wait_group 1;\n" ::: "memory"); }
        __syncthreads();
        if (kt + 2 < NKTX) load_tile(kt + 2, (kt + 2) % 3);

        const int stage = kt % 3;
        const uint32_t Ab = sA_u + stage * XG_A_STAGE + arow;
        const uint32_t Bb = sB_u + stage * XG_B_STAGE + nw * 4096 + lane * 8;
#pragma unroll
        for (int sub = 0; sub < 2; sub++) {
            uint32_t a0[4], a1[4];
            LDSM4(a0, Ab + sub * 32);
            LDSM4(a1, Ab + 16 * 80 + sub * 32);
#pragma unroll
            for (int ni = 0; ni < 8; ni++) {
                uint32_t b0, b1;
                LDSV2(b0, b1, Bb + (sub * 8 + ni) * 256);
                MMA_F16(acc[0][ni], a0, b0, b1);
                MMA_F16(acc[1][ni], a1, b0, b1);
            }
        }
    }

    const int g = lane >> 2, t4 = lane & 3;
    const int cg = cg0 + nw;
#pragma unroll
    for (int ni = 0; ni < 8; ni++) {
        const int gc0 = ni * 8 + t4 * 2;          // local col = ui*4 + gate (even)
        const int gate = gc0 & 3, ui = gc0 >> 2;
        const float bv0 = bias[gate * HSZ + cg * UPC + ui];
        const float bv1 = bias[(gate + 1) * HSZ + cg * UPC + ui];
#pragma unroll
        for (int mi = 0; mi < 2; mi++) {
#pragma unroll
            for (int rr = 0; rr < 2; rr++) {
                const int r = mw * 32 + mi * 16 + rr * 8 + g;
                const int m = bx * 128 + r;
                const int b = m >> 9, t = m & 511;
                __half2 pv = __halves2half2(
                    __float2half_rn(acc[mi][ni][rr * 2]     + bv0),
                    __float2half_rn(acc[mi][ni][rr * 2 + 1] + bv1));
                __half2* dst = reinterpret_cast<__half2*>(
                    g_xg + (((size_t)t * NCG + cg) * BATCH + b) * 64 + gc0);
                *dst = pv;
            }
        }
    }
}

// ---------------- persistent recurrent kernel ----------------
// 128 CTAs x 256 threads (8 warps = 2M x 4N, NO K-split). Warp tile
// m16 x n16 x k1024: accumulators are FINAL gates -> warp-local epilogue,
// one __syncthreads/step, per-warp red.release to the CTA flag (target 8/step).
__global__ void __launch_bounds__(256, 1) lstm_persist(
    float* __restrict__ out, int write_final)
{
    extern __shared__ char smem[];

    const int tid  = threadIdx.x;
    const int warp = tid >> 5;
    const int lane = tid & 31;
    const int cb   = blockIdx.x;
    const int cg   = cb & 63;
    const int bg   = cb >> 6;
    const int mw   = warp >> 2;          // M half (16 rows)
    const int nw   = warp & 3;           // N quarter (n16)

    // resident W fragment preload (once): 128KB
    {
        const uint4* sh = reinterpret_cast<const uint4*>(g_Whf + (size_t)cg * WORDS_H);
        uint4* dh = reinterpret_cast<uint4*>(smem);
        for (int i = tid; i < WORDS_H / 4; i += 256) dh[i] = sh[i];
    }

    const uint32_t sW_u = (uint32_t)__cvta_generic_to_shared(smem);
    const uint32_t sA_u = sW_u + SM_A;
    const uint32_t abase = sA_u
        + (uint32_t)((mw * 16 + (lane & 15)) * A_STRIDE + (lane >> 4) * 16);
    const int l_row = tid >> 3;          // loader row 0..31
    const int l_cc  = tid & 7;

    // epilogue identity: parity pair exchange gives one thread all 4 gates
    const int t4  = lane & 3;
    const int pr  = t4 & 1;
    const int uil = pr ? (t4 >> 1) + 2 : (t4 >> 1);
    const int ui_g = nw * 4 + uil;              // unit within cg: 0..15
    const int u    = cg * UPC + ui_g;
    const int b0   = bg * MB + mw * 16 + (lane >> 2);   // rh=0 batch
    const int b1   = b0 + 8;                            // rh=1 batch
    float cst0 = 0.0f, cst1 = 0.0f;

    const unsigned* myspin = (const unsigned*)(g_flags + (bg * NCG + (tid & 63)) * 32);
    unsigned* myflag = g_flags + cb * 32;

    __syncthreads();

    for (int t = 0; t < SEQ; t++) {
        const int rb = t & 1, wb = rb ^ 1;

        // spin: all same-bg CTAs finished step t-1 (8 warp-arrivals each).
        // Also guarantees own warps are done reading the old A stage.
        {
            const unsigned tgt = 8u * (unsigned)t;
            unsigned v;
            do {
                asm volatile("ld.acquire.gpu.u32 %0, [%1];" : "=r"(v) : "l"(myspin) : "memory");
            } while (v < tgt);
        }

        // cooperative A load: 32 rows x 2048B (k1024), 16 chunks/thread
        {
            const __half* src = g_h[rb] + (size_t)(bg * MB + l_row) * HSZ + l_cc * 8;
            const uint32_t dst = sA_u + l_row * A_STRIDE + l_cc * 16;
#pragma unroll
            for (int j = 0; j < 16; j++)
                cp_async16_s(dst + j * 128, src + j * 64);
            cp_commit();
        }

        // xg prefetch: 4 contiguous halfs (all gates of (b, ui_g)) per batch
        float xg0[4], xg1[4];
        {
            const size_t base = (((size_t)t * NCG + cg) * BATCH) * 64 + ui_g * 4;
            const __half2* p0 = reinterpret_cast<const __half2*>(g_xg + base + (size_t)b0 * 64);
            const __half2* p1 = reinterpret_cast<const __half2*>(g_xg + base + (size_t)b1 * 64);
            float2 a, b;
            a = __half22float2(p0[0]); b = __half22float2(p0[1]);
            xg0[0] = a.x; xg0[1] = a.y; xg0[2] = b.x; xg0[3] = b.y;
            a = __half22float2(p1[0]); b = __half22float2(p1[1]);
            xg1[0] = a.x; xg1[1] = a.y; xg1[2] = b.x; xg1[3] = b.y;
        }

        asm volatile("cp.async.wait_group 0;\n" ::: "memory");
        __syncthreads();   // the ONLY CTA sync: all loaders' A data visible

        // mainloop: k1024, warp-local, no syncs
        float acc[2][4] = {{0.f,0.f,0.f,0.f},{0.f,0.f,0.f,0.f}};
#pragma unroll 8
        for (int k16 = 0; k16 < 64; k16++) {
            uint32_t a0[4];
            LDSM4(a0, abase + k16 * 32);
#pragma unroll
            for (int n8l = 0; n8l < 2; n8l++) {
                const int n8 = nw * 2 + n8l;
                const uint32_t Bb = sW_u + (uint32_t)((k16 * 8 + n8) * 256 + lane * 8);
                uint32_t b0r, b1r;
                LDSV2(b0r, b1r, Bb);
                MMA_F16(acc[n8l], a0, b0r, b1r);
            }
        }

        // pair exchange: even lane keeps ui=uil (gates 0,1), gets gates 2,3;
        // odd lane keeps ui=uil (gates 2,3), gets gates 0,1.
        float recv[4];
#pragma unroll
        for (int j = 0; j < 4; j++) {
            float send = pr ? acc[0][j] : acc[1][j];
            recv[j] = __shfl_xor_sync(0xffffffffu, send, 1);
        }

        float hv[2], cv[2];
#pragma unroll
        for (int rh = 0; rh < 2; rh++) {
            const float* xg = rh ? xg1 : xg0;
            float g0 = pr ? recv[rh * 2]     : acc[0][rh * 2];
            float g1 = pr ? recv[rh * 2 + 1] : acc[0][rh * 2 + 1];
            float g2 = pr ? acc[1][rh * 2]     : recv[rh * 2];
            float g3 = pr ? acc[1][rh * 2 + 1] : recv[rh * 2 + 1];
            float fg = sigmoidf_(g0 + xg[0]);
            float ig = sigmoidf_(g1 + xg[1]);
            float cc = tanhf    (g2 + xg[2]);
            float og = sigmoidf_(g3 + xg[3]);
            float& cst = rh ? cst1 : cst0;
            cst = fg * cst + ig * cc;
            float h = og * tanhf(cst);
            const int b = rh ? b1 : b0;
            g_h[wb][b * HSZ + u] = __float2half_rn(h);
            hv[rh] = h; cv[rh] = cst;
        }

        // warp-local release: warp memory-sync, then one lane adds 1 (release)
        __syncwarp();
        if (lane == 0) {
            asm volatile("red.release.gpu.global.add.u32 [%0], %1;"
                         :: "l"(myflag), "r"(1u) : "memory");
        }

        // non-critical output stores after release
#pragma unroll
        for (int rh = 0; rh < 2; rh++) {
            const int b = rh ? b1 : b0;
            out[((size_t)b * SEQ + t) * HSZ + u] = hv[rh];
            if (t == SEQ - 1 && write_final) {
                out[(size_t)BATCH * SEQ * HSZ + b * HSZ + u]               = hv[rh];
                out[(size_t)BATCH * SEQ * HSZ + BATCH * HSZ + b * HSZ + u] = cv[rh];
            }
        }
    }
}

// ---------------- launch ----------------
extern "C" void kernel_launch(void* const* d_in, const int* in_sizes, int n_in,
                              void* d_out, int out_size) {
    const float* x = nullptr;
    const float* W = nullptr;
    const float* bias = nullptr;
    for (int i = 0; i < n_in; i++) {
        if (in_sizes[i] == BATCH * SEQ * ISZ)           x = (const float*)d_in[i];
        else if (in_sizes[i] == (ISZ + HSZ) * GSZ)      W = (const float*)d_in[i];
        else if (in_sizes[i] == GSZ)                    bias = (const float*)d_in[i];
    }
    float* out = (float*)d_out;
    const long long full = (long long)BATCH * SEQ * HSZ + 2LL * BATCH * HSZ;
    const int write_final = (out_size >= full) ? 1 : 0;

    cudaFuncSetAttribute(lstm_persist, cudaFuncAttributeMaxDynamicSharedMemorySize, SMEM_TOTAL);
    cudaFuncSetAttribute(xw_gemm, cudaFuncAttributeMaxDynamicSharedMemorySize, XG_SMEM);

    {
        int n4 = BATCH * SEQ * ISZ / 4;
        prep_x<<<(n4 + 255) / 256, 256>>>(x);
    }
    {
        long long n = (long long)NCG * WORDS_H;
        prep_wh<<<(unsigned)((n + 255) / 256), 256>>>(W);
    }
    {
        long long n = (long long)NCG * WORDS_X;
        prep_wx<<<(unsigned)((n + 255) / 256), 256>>>(W);
    }
    prep_state<<<(2 * BATCH * HSZ + 255) / 256, 256>>>();

    {
        dim3 grid(SEQ * BATCH / 128, NCG / CBQ);
        xw_gemm<<<grid, 256, XG_SMEM>>>(bias);
    }

    lstm_persist<<<NCTA, 256, SMEM_TOTAL>>>(out, write_final);
}

// round 16
// speedup vs baseline: 1.1892x; 1.1892x over previous
#include <cuda_runtime.h>
#include <cuda_bf16.h>
#include <cuda_fp16.h>
#include <cstdint>

// ---------------- problem dims ----------------
#define BATCH 64
#define SEQ   512
#define ISZ   512
#define HSZ   1024
#define GSZ   4096
#define NCTA  128            // 2 batch-groups x 64 column-groups
#define NCG   64             // column groups
#define UPC   16             // hidden units per cg (64 gate cols)
#define MB    32             // batches per CTA
#define WORDS_H (64 * 8 * 32 * 2)      // 32768 u32 per cg (fp16 frags, K=1024, N=64)
#define WORDS_X (32 * 8 * 32 * 2)      // 16384 u32 per cg (K=512, N=64)
#define CBQ   2              // cg blocks per xw CTA
#define NKTX  16             // k32 tiles in x GEMM

// recurrent smem layout (bytes): W 128KB, then 2 A stages (32 rows x k512)
#define SM_A     131072
#define A_STRIDE 1040                   // 1024B data + 16B pad
#define A_STG    (32 * A_STRIDE)        // 33280 per stage
#define SMEM_TOTAL (SM_A + 2 * A_STG)   // 197632
// gate-partial overlay on A stage 0: [4][32][65] floats = 33280 B exactly
#define SG_PLANE 2080                   // 32*65 floats per kw plane

// xw smem (dynamic): 3 stages A + 3 stages B
#define XG_A_STAGE 10240     // 128 rows x 80B (fp16 k32)
#define XG_B_STAGE 8192      // 2 cg x 4KB
#define XG_SMEM (3 * (XG_A_STAGE + XG_B_STAGE))   // 55296

// ---------------- persistent device scratch ----------------
__device__ __align__(256) unsigned g_Whf[(size_t)NCG * WORDS_H];      // 8 MB
__device__ __align__(256) unsigned g_Wxf[(size_t)NCG * WORDS_X];      // 4 MB
__device__ __align__(256) __half   g_xh[(size_t)BATCH * SEQ * ISZ];   // 32 MB
__device__ __align__(256) __half   g_xg[(size_t)SEQ * NCG * BATCH * 64]; // 256 MB
__device__ __align__(256) __half   g_h[2][BATCH * HSZ];               // fp16 h, ping-pong
__device__ __align__(128) unsigned g_flags[NCTA * 32];

// ---------------- helpers ----------------
__device__ __forceinline__ void cp_async16_s(uint32_t dst_smem, const void* src) {
    asm volatile("cp.async.cg.shared.global [%0], [%1], 16;\n"
                 :: "r"(dst_smem), "l"(src) : "memory");
}
__device__ __forceinline__ void cp_commit() {
    asm volatile("cp.async.commit_group;\n" ::: "memory");
}
// cancellation-safe fast activations (abs err <= ~3e-7; norm-irrelevant)
__device__ __forceinline__ float fsig(float v) {
    return __fdividef(1.0f, 1.0f + __expf(-v));     // no subtraction -> safe
}
__device__ __forceinline__ float ftanh2(float v) {
    v = fminf(fmaxf(v, -30.0f), 30.0f);             // keep exp finite
    float u = __expf(-2.0f * v);
    return __fdividef(1.0f - u, 1.0f + u);          // (1-u)/(1+u): abs err ~2e-7
}

#define LDSM4(R, ADDR) \
    asm volatile("ldmatrix.sync.aligned.m8n8.x4.shared.b16 {%0,%1,%2,%3},[%4];" \
                 : "=r"((R)[0]), "=r"((R)[1]), "=r"((R)[2]), "=r"((R)[3]) : "r"(ADDR))

#define MMA_F16(ACC, A, B0, B1) \
    asm volatile("mma.sync.aligned.m16n8k16.row.col.f32.f16.f16.f32 " \
                 "{%0,%1,%2,%3},{%4,%5,%6,%7},{%8,%9},{%0,%1,%2,%3};" \
                 : "+f"((ACC)[0]), "+f"((ACC)[1]), "+f"((ACC)[2]), "+f"((ACC)[3]) \
                 : "r"((A)[0]), "r"((A)[1]), "r"((A)[2]), "r"((A)[3]), "r"(B0), "r"(B1))

#define LDSV2(R0, R1, ADDR) \
    asm volatile("ld.shared.v2.u32 {%0,%1},[%2];" : "=r"(R0), "=r"(R1) : "r"(ADDR))

// ---------------- prep kernels ----------------
__global__ void prep_x(const float* __restrict__ x) {
    size_t i = (size_t)blockIdx.x * blockDim.x + threadIdx.x;
    size_t n4 = (size_t)BATCH * SEQ * ISZ / 4;
    if (i >= n4) return;
    float4 v = reinterpret_cast<const float4*>(x)[i];
    __half2* d = reinterpret_cast<__half2*>(g_xh);
    d[i * 2]     = __halves2half2(__float2half_rn(v.x), __float2half_rn(v.y));
    d[i * 2 + 1] = __halves2half2(__float2half_rn(v.z), __float2half_rn(v.w));
}

// Wh fragments fp16 (K=1024, N=64 per cg).
__global__ void prep_wh(const float* __restrict__ W) {
    size_t w = (size_t)blockIdx.x * blockDim.x + threadIdx.x;
    if (w >= (size_t)NCG * WORDS_H) return;
    int q    = (int)(w & 1);
    int lane = (int)((w >> 1) & 31);
    int n8   = (int)((w >> 6) & 7);
    int k16  = (int)((w >> 9) & 63);
    int cg   = (int)(w >> 15);
    int k  = k16 * 16 + (lane & 3) * 2 + q * 8;
    int nl = n8 * 8 + (lane >> 2);
    int col = (nl >> 4) * HSZ + cg * UPC + (nl & 15);
    __half h0 = __float2half_rn(W[(size_t)(ISZ + k) * GSZ + col]);
    __half h1 = __float2half_rn(W[(size_t)(ISZ + k + 1) * GSZ + col]);
    __half2 ph = __halves2half2(h0, h1);
    g_Whf[w] = *reinterpret_cast<unsigned*>(&ph);
}

// Wx fragments fp16 (K=512, N=64 per cg).
__global__ void prep_wx(const float* __restrict__ W) {
    size_t w = (size_t)blockIdx.x * blockDim.x + threadIdx.x;
    if (w >= (size_t)NCG * WORDS_X) return;
    int q    = (int)(w & 1);
    int lane = (int)((w >> 1) & 31);
    int n8   = (int)((w >> 6) & 7);
    int k16  = (int)((w >> 9) & 31);
    int cg   = (int)(w >> 14);
    int k  = k16 * 16 + (lane & 3) * 2 + q * 8;
    int nl = n8 * 8 + (lane >> 2);
    int col = (nl >> 4) * HSZ + cg * UPC + (nl & 15);
    __half h0 = __float2half_rn(W[(size_t)k * GSZ + col]);
    __half h1 = __float2half_rn(W[(size_t)(k + 1) * GSZ + col]);
    __half2 ph = __halves2half2(h0, h1);
    g_Wxf[w] = *reinterpret_cast<unsigned*>(&ph);
}

__global__ void prep_state() {
    int i = blockIdx.x * blockDim.x + threadIdx.x;
    if (i < 2 * BATCH * HSZ) (&g_h[0][0])[i] = __float2half(0.0f);
    if (i < NCTA * 32) g_flags[i] = 0u;
}

// ---------------- xg precompute GEMM (fp16, K=512) — unchanged ------------
__global__ void __launch_bounds__(256) xw_gemm(const float* __restrict__ bias) {
    extern __shared__ char smem[];
    const uint32_t sA_u = (uint32_t)__cvta_generic_to_shared(smem);
    const uint32_t sB_u = sA_u + 3 * XG_A_STAGE;

    const int tid  = threadIdx.x;
    const int warp = tid >> 5;
    const int lane = tid & 31;
    const int bx   = blockIdx.x;
    const int cg0  = blockIdx.y * CBQ;
    const int mw   = warp >> 1;      // 4 M-warps (32 rows each)
    const int nw   = warp & 1;       // cg select (64 cols each)

    float acc[2][8][4];
#pragma unroll
    for (int a = 0; a < 2; a++)
#pragma unroll
        for (int b = 0; b < 8; b++)
#pragma unroll
            for (int c = 0; c < 4; c++) acc[a][b][c] = 0.0f;

    auto load_tile = [&](int kt, int stage) {
        const int k0 = kt * 32;
#pragma unroll
        for (int j = 0; j < 2; j++) {
            int ch = tid + j * 256;
            int rr = ch >> 2, cc = ch & 3;
            cp_async16_s(sA_u + stage * XG_A_STAGE + rr * 80 + cc * 16,
                         g_xh + ((size_t)(bx * 128 + rr)) * ISZ + k0 + cc * 8);
        }
#pragma unroll
        for (int j = 0; j < 2; j++) {
            int ch = tid + j * 256;
            int q = ch >> 8, ww = ch & 255;
            const unsigned* src = g_Wxf + (size_t)(cg0 + q) * WORDS_X + kt * 1024 + ww * 4;
            cp_async16_s(sB_u + stage * XG_B_STAGE + q * 4096 + ww * 16, src);
        }
        cp_commit();
    };

    load_tile(0, 0);
    load_tile(1, 1);

    const uint32_t arow = (uint32_t)((mw * 32 + (lane & 15)) * 80 + (lane >> 4) * 16);

#pragma unroll
    for (int kt = 0; kt < NKTX; kt++) {
        if (kt == NKTX - 1) { asm volatile("cp.async.wait_group 0;\n" ::: "memory"); }
        else                { asm volatile("cp.async.wait_group 1;\n" ::: "memory"); }
        __syncthreads();
        if (kt + 2 < NKTX) load_tile(kt + 2, (kt + 2) % 3);

        const int stage = kt % 3;
        const uint32_t Ab = sA_u + stage * XG_A_STAGE + arow;
        const uint32_t Bb = sB_u + stage * XG_B_STAGE + nw * 4096 + lane * 8;
#pragma unroll
        for (int sub = 0; sub < 2; sub++) {
            uint32_t a0[4], a1[4];
            LDSM4(a0, Ab + sub * 32);
            LDSM4(a1, Ab + 16 * 80 + sub * 32);
#pragma unroll
            for (int ni = 0; ni < 8; ni++) {
                uint32_t b0, b1;
                LDSV2(b0, b1, Bb + (sub * 8 + ni) * 256);
                MMA_F16(acc[0][ni], a0, b0, b1);
                MMA_F16(acc[1][ni], a1, b0, b1);
            }
        }
    }

    const int g = lane >> 2, t4 = lane & 3;
    const int cg = cg0 + nw;
#pragma unroll
    for (int ni = 0; ni < 8; ni++) {
        const int gc0 = ni * 8 + t4 * 2;          // local col = gate*16+ui
        const int gate = gc0 >> 4, ui = gc0 & 15;
        const float bv0 = bias[gate * HSZ + cg * UPC + ui];
        const float bv1 = bias[gate * HSZ + cg * UPC + ui + 1];
#pragma unroll
        for (int mi = 0; mi < 2; mi++) {
#pragma unroll
            for (int rr = 0; rr < 2; rr++) {
                const int r = mw * 32 + mi * 16 + rr * 8 + g;
                const int m = bx * 128 + r;
                const int b = m >> 9, t = m & 511;
                __half2 pv = __halves2half2(
                    __float2half_rn(acc[mi][ni][rr * 2]     + bv0),
                    __float2half_rn(acc[mi][ni][rr * 2 + 1] + bv1));
                __half2* dst = reinterpret_cast<__half2*>(
                    g_xg + (((size_t)t * NCG + cg) * BATCH + b) * 64 + gc0);
                *dst = pv;
            }
        }
    }
}

// ---------------- persistent recurrent kernel ----------------
// 128 CTAs x 256 threads (8 warps = 4K x 2N). CTA (bg,cg): 32 batches x 64
// gate cols, K=1024. 128KB W resident; 2 x k512 A stages issued up-front.
// COLLECTIVE barrier (R12-proven): tid<64 each verify one same-bg flag, then
// __syncthreads gates all loads. Per-warp red.release (target 8 arrivals/CTA
// /step) removes the pre-release CTA sync. Fast cancellation-safe activations.
__global__ void __launch_bounds__(256, 1) lstm_persist(
    float* __restrict__ out, int write_final)
{
    extern __shared__ char smem[];
    float* sG4 = reinterpret_cast<float*>(smem + SM_A);   // [4][32][65] overlay

    const int tid  = threadIdx.x;
    const int warp = tid >> 5;
    const int lane = tid & 31;
    const int cb   = blockIdx.x;
    const int cg   = cb & 63;
    const int bg   = cb >> 6;
    const int kw   = warp & 3;           // K slice (k128 per stage)
    const int nw   = warp >> 2;          // N half (n32)

    // resident W fragment preload (once): 128KB
    {
        const uint4* sh = reinterpret_cast<const uint4*>(g_Whf + (size_t)cg * WORDS_H);
        uint4* dh = reinterpret_cast<uint4*>(smem);
        for (int i = tid; i < WORDS_H / 4; i += 256) dh[i] = sh[i];
    }

    float cst0 = 0.0f, cst1 = 0.0f;

    const uint32_t sW_u = (uint32_t)__cvta_generic_to_shared(smem);
    const uint32_t sA_u = sW_u + SM_A;
    const uint32_t abase = (uint32_t)((lane & 15) * A_STRIDE + kw * 256 + (lane >> 4) * 16);
    const int l_row = tid >> 3;          // 0..31
    const int l_cc  = tid & 7;           // 0..7

    // collective spin: thread tid<64 verifies flag of same-bg CTA (bg,tid)
    const unsigned* myspin = (const unsigned*)(g_flags + (bg * NCG + (tid & 63)) * 32);
    unsigned* myflag = g_flags + cb * 32;

    __syncthreads();

    for (int t = 0; t < SEQ; t++) {
        const int rb = t & 1, wb = rb ^ 1;
        float acc[2][4][4];
#pragma unroll
        for (int a = 0; a < 2; a++)
#pragma unroll
            for (int b = 0; b < 4; b++)
#pragma unroll
                for (int c = 0; c < 4; c++) acc[a][b][c] = 0.0f;

        // xg prefetch (flag-independent): overlaps the spin wait
        float xg[2][4];
#pragma unroll
        for (int pp = 0; pp < 2; pp++) {
            const int p  = tid + pp * 256;
            const int bl = p >> 4, ui = p & 15;
            const __half* xgp = g_xg +
                (((size_t)t * NCG + cg) * BATCH + bg * MB + bl) * 64;
            xg[pp][0] = __half2float(xgp[ui]);
            xg[pp][1] = __half2float(xgp[16 + ui]);
            xg[pp][2] = __half2float(xgp[32 + ui]);
            xg[pp][3] = __half2float(xgp[48 + ui]);
        }

        // COLLECTIVE barrier: 64 threads cover all 64 same-bg flags (8 warp-
        // arrivals per CTA per step), then a CTA sync gates every load below.
        if (tid < NCG) {
            const unsigned tgt = 8u * (unsigned)t;
            unsigned v;
            do {
                asm volatile("ld.acquire.gpu.u32 %0, [%1];" : "=r"(v) : "l"(myspin) : "memory");
            } while (v < tgt);
        }
        __syncthreads();

        // both A stages issued up-front (stage-1 latency overlaps stage-0's)
        {
            const __half* src0 = g_h[rb] + (size_t)(bg * MB + l_row) * HSZ + l_cc * 8;
            const uint32_t dst0 = sA_u + l_row * A_STRIDE + l_cc * 16;
#pragma unroll
            for (int j = 0; j < 8; j++)
                cp_async16_s(dst0 + j * 128, src0 + j * 64);
            cp_commit();
#pragma unroll
            for (int j = 0; j < 8; j++)
                cp_async16_s(dst0 + A_STG + j * 128, src0 + 512 + j * 64);
            cp_commit();
        }

#pragma unroll
        for (int s = 0; s < 2; s++) {
            if (s == 0) { asm volatile("cp.async.wait_group 1;\n" ::: "memory"); }
            else        { asm volatile("cp.async.wait_group 0;\n" ::: "memory"); }
            __syncthreads();

            const uint32_t Ab = sA_u + s * A_STG + abase;
#pragma unroll
            for (int j = 0; j < 8; j++) {
                uint32_t a0[4], a1[4];
                LDSM4(a0, Ab + j * 32);
                LDSM4(a1, Ab + 16 * A_STRIDE + j * 32);
                const int k16g = s * 32 + kw * 8 + j;
#pragma unroll
                for (int ni = 0; ni < 4; ni++) {
                    const int n8g = nw * 4 + ni;
                    const uint32_t Bb = sW_u + (uint32_t)((k16g * 8 + n8g) * 256 + lane * 8);
                    uint32_t b0, b1;
                    LDSV2(b0, b1, Bb);
                    MMA_F16(acc[0][ni], a0, b0, b1);
                    MMA_F16(acc[1][ni], a1, b0, b1);
                }
            }
        }

        // K-partial store into padded smem [4][32][65] (overlay on A stage 0;
        // safe: all warps passed the s=1 sync, so stage-0 reads are done)
        {
            const int g = lane >> 2, t4 = lane & 3;
#pragma unroll
            for (int mi = 0; mi < 2; mi++)
#pragma unroll
                for (int ni = 0; ni < 4; ni++) {
                    const int r = mi * 16 + g;
                    const int c = (nw * 4 + ni) * 8 + t4 * 2;
                    float* p = sG4 + kw * SG_PLANE + r * 65 + c;
                    p[0]          = acc[mi][ni][0];
                    p[1]          = acc[mi][ni][1];
                    p[8 * 65]     = acc[mi][ni][2];
                    p[8 * 65 + 1] = acc[mi][ni][3];
                }
        }
        __syncthreads();

        // reduce 4 K-partials + cell update; store g_h (critical path)
        float hval[2];
        int   bidx[2], uidx[2];
#pragma unroll
        for (int pp = 0; pp < 2; pp++) {
            const int p  = tid + pp * 256;
            const int bl = p >> 4, ui = p & 15;
            float gf = 0.f, gi = 0.f, gc_ = 0.f, go = 0.f;
#pragma unroll
            for (int k = 0; k < 4; k++) {
                const float* q = sG4 + k * SG_PLANE + bl * 65;
                gf  += q[ui];
                gi  += q[16 + ui];
                gc_ += q[32 + ui];
                go  += q[48 + ui];
            }
            float fg = fsig(gf  + xg[pp][0]);
            float ig = fsig(gi  + xg[pp][1]);
            float cg2 = ftanh2(gc_ + xg[pp][2]);
            float og = fsig(go  + xg[pp][3]);
            float& cst = pp ? cst1 : cst0;
            cst = fg * cst + ig * cg2;
            float h = og * ftanh2(cst);
            const int b = bg * MB + bl;
            const int u = cg * UPC + ui;
            g_h[wb][b * HSZ + u] = __float2half_rn(h);
            hval[pp] = h; bidx[pp] = b; uidx[pp] = u;
        }

        // per-warp release: warp memory ordering via __syncwarp, then one
        // release-add per warp (consumers wait for 8 arrivals = whole CTA)
        __syncwarp();
        if (lane == 0) {
            asm volatile("red.release.gpu.global.add.u32 [%0], %1;"
                         :: "l"(myflag), "r"(1u) : "memory");
        }

        // non-critical output stores overlap other CTAs' progress
#pragma unroll
        for (int pp = 0; pp < 2; pp++) {
            out[((size_t)bidx[pp] * SEQ + t) * HSZ + uidx[pp]] = hval[pp];
            if (t == SEQ - 1 && write_final) {
                out[(size_t)BATCH * SEQ * HSZ + bidx[pp] * HSZ + uidx[pp]] = hval[pp];
                out[(size_t)BATCH * SEQ * HSZ + BATCH * HSZ + bidx[pp] * HSZ + uidx[pp]]
                    = pp ? cst1 : cst0;
            }
        }
    }
}

// ---------------- launch ----------------
extern "C" void kernel_launch(void* const* d_in, const int* in_sizes, int n_in,
                              void* d_out, int out_size) {
    const float* x = nullptr;
    const float* W = nullptr;
    const float* bias = nullptr;
    for (int i = 0; i < n_in; i++) {
        if (in_sizes[i] == BATCH * SEQ * ISZ)           x = (const float*)d_in[i];
        else if (in_sizes[i] == (ISZ + HSZ) * GSZ)      W = (const float*)d_in[i];
        else if (in_sizes[i] == GSZ)                    bias = (const float*)d_in[i];
    }
    float* out = (float*)d_out;
    const long long full = (long long)BATCH * SEQ * HSZ + 2LL * BATCH * HSZ;
    const int write_final = (out_size >= full) ? 1 : 0;

    cudaFuncSetAttribute(lstm_persist, cudaFuncAttributeMaxDynamicSharedMemorySize, SMEM_TOTAL);
    cudaFuncSetAttribute(xw_gemm, cudaFuncAttributeMaxDynamicSharedMemorySize, XG_SMEM);

    {
        int n4 = BATCH * SEQ * ISZ / 4;
        prep_x<<<(n4 + 255) / 256, 256>>>(x);
    }
    {
        long long n = (long long)NCG * WORDS_H;
        prep_wh<<<(unsigned)((n + 255) / 256), 256>>>(W);
    }
    {
        long long n = (long long)NCG * WORDS_X;
        prep_wx<<<(unsigned)((n + 255) / 256), 256>>>(W);
    }
    prep_state<<<(2 * BATCH * HSZ + 255) / 256, 256>>>();

    {
        dim3 grid(SEQ * BATCH / 128, NCG / CBQ);
        xw_gemm<<<grid, 256, XG_SMEM>>>(bias);
    }

    lstm_persist<<<NCTA, 256, SMEM_TOTAL>>>(out, write_final);
}